// round 6
// baseline (speedup 1.0000x reference)
#include <cuda_runtime.h>

#define TPB  256
#define RPB  256                          // rows per block = 1 per thread
#define SROW 25                           // staging stride (odd -> STS conflict-free)
#define STAGE_W  (RPB * SROW)             // 6400 words
#define FLAG_OFS STAGE_W
#define SMEM_W   (FLAG_OFS + 8)           // ~25.6KB -> 8 blocks/SM

// Global coefficient tables (zero-initialized; all blocks write identical bytes).
// Layout per h (12 floats, 16B-aligned): pd: [8x 0.1*P, c0, pad3]
//                                        pz: [8x pe*sp(P), a1, zm, pad2]
__device__ __align__(16) float g_pd[24 * 12];
__device__ __align__(16) float g_pz[24 * 12];

__device__ __forceinline__ float sp_f(float x) {      // fast softplus
    return fmaxf(x, 0.0f) + __logf(1.0f + __expf(-fabsf(x)));
}
__device__ __forceinline__ float sig_f(float x) {
    return 1.0f / (1.0f + __expf(-x));
}

__global__ void __launch_bounds__(TPB, 8)
cb_fused(const float* __restrict__ x, float* __restrict__ out, int B,
         const float* __restrict__ W,  const float* __restrict__ P,
         const float* __restrict__ bv, const float* __restrict__ bz,
         const float* __restrict__ e,  const float* __restrict__ ep,
         const float* __restrict__ cx, const float* __restrict__ cu,
         const float* __restrict__ cU, const float* __restrict__ v0,
         const float* __restrict__ X0, const float* __restrict__ U0)
{
    __shared__ float sm[SMEM_W];
    const int t = threadIdx.x;
    const int row = blockIdx.x * RPB + t;       // lane <-> consecutive batch row

    // ---- x loads first (coalesced, streaming), latency overlaps prologue ----
    float xa[8];
    #pragma unroll
    for (int i = 0; i < 8; ++i)
        xa[i] = (row < B) ? __ldcs(x + (size_t)i * (size_t)B + row) : 0.0f;

    // ---- prologue: batch-invariant math; results -> GLOBAL coef tables ----
    // All blocks compute and write IDENTICAL values (benign race); each block
    // writes before it reads, so reads below are always valid.
    {
        float* rS  = sm;            // 24   (aliases staging region, pre-sync)
        float* wS  = sm + 24;       // 24
        float* pkr = sm + 48;       // 192
        float* pwr = sm + 240;      // 192

        if (t < 24) {
            float v0v = v0[t];
            float rv  = sig_f(v0v);
            rS[t] = rv;
            float zx = 0.001f + 0.099f * sig_f(cx[t]);
            float X  = zx + (1.0f - zx) * X0[t] - U0[t] * X0[t] * rv;  // delta_t=1
            float zu   = 0.001f + 0.099f * sig_f(cu[t]);
            float Ucap = 0.9f * sig_f(cU[t]);
            float U = Ucap * zu + (1.0f - zu) * U0[t] + Ucap * (1.0f - U0[t]) * rv;
            U = fminf(fmaxf(U, Ucap), 1.0f);
            wS[t] = U * X * rv;
            g_pz[t * 12 + 9] = -0.1f * v0v;                 // zm
        }
        if (t == 0) {
            int f = 0;
            #pragma unroll
            for (int j = 0; j < 24; ++j) f |= (v0[j] != 0.0f);
            sm[FLAG_OFS] = (float)f;
        }
        __syncthreads();

        if (t < 192) {
            const int h = t >> 3;                // 0..23
            const int i = t & 7;                 // 0..7
            float kr = 0.0f, wur = 0.0f;
            #pragma unroll
            for (int jj = 0; jj < 3; ++jj) {
                int j = i * 3 + jj;
                float Wv = W[h * 24 + j];
                kr  += sp_f(Wv) * rS[j];
                wur += Wv * wS[j];
            }
            pkr[h * 8 + i] = kr;
            pwr[h * 8 + i] = wur;
            float pe = sp_f(ep[0]);
            float Pv = P[h * 8 + i];             // P is (H, IN) row-major
            g_pd[h * 12 + i] = 0.1f * Pv;
            g_pz[h * 12 + i] = pe * sp_f(Pv);
        }
        __syncthreads();

        if (t < 24) {
            float kr = 0.0f, wur = 0.0f;
            #pragma unroll
            for (int k = 0; k < 8; ++k) { kr += pkr[t * 8 + k]; wur += pwr[t * 8 + k]; }
            float ke = sp_f(e[0]);
            g_pz[t * 12 + 8] = ke * kr + bz[t];                    // a1
            g_pd[t * 12 + 8] = v0[t] + 0.1f * (wur + bv[t]);       // c0
        }
        __syncthreads();
    }

    const bool slow = (sm[FLAG_OFS] != 0.0f);

    // ---- main: 24 h per row; coefs via uniform LDG.128 (1 wf each, L1-hit) ----
    #pragma unroll
    for (int h = 0; h < 24; ++h) {
        const float4* pd4 = (const float4*)(g_pd + h * 12);
        const float4 wA = __ldg(pd4);
        const float4 wB = __ldg(pd4 + 1);
        const float4 wC = __ldg(pd4 + 2);      // wC.x = c0
        float v = wC.x;
        v = fmaf(wA.x, xa[0], v);
        v = fmaf(wA.y, xa[1], v);
        v = fmaf(wA.z, xa[2], v);
        v = fmaf(wA.w, xa[3], v);
        v = fmaf(wB.x, xa[4], v);
        v = fmaf(wB.y, xa[5], v);
        v = fmaf(wB.z, xa[6], v);
        v = fmaf(wB.w, xa[7], v);

        if (slow) {
            // General case (v0 != 0): v += sig(a1 + Pz@x) * (-0.1*v0[h]). Exact.
            const float4* pz4 = (const float4*)(g_pz + h * 12);
            const float4 zA = __ldg(pz4);
            const float4 zB = __ldg(pz4 + 1);
            const float4 zC = __ldg(pz4 + 2);  // zC.x = a1, zC.y = zm
            float a = zC.x;
            a = fmaf(zA.x, xa[0], a);
            a = fmaf(zA.y, xa[1], a);
            a = fmaf(zA.z, xa[2], a);
            a = fmaf(zA.w, xa[3], a);
            a = fmaf(zB.x, xa[4], a);
            a = fmaf(zB.y, xa[5], a);
            a = fmaf(zB.z, xa[6], a);
            a = fmaf(zB.w, xa[7], a);
            v = fmaf(zC.y, sig_f(a), v);
        }

        sm[t * SROW + h] = v;                 // stride 25: conflict-free STS
    }
    __syncthreads();

    // ---- coalesced writeout: block owns float4 range [blockIdx*1536, +1536) ----
    const unsigned totF4  = (unsigned)B * 6u;
    const unsigned baseF4 = (unsigned)blockIdx.x * 1536u;
    float4* out4 = (float4*)out;
    #pragma unroll
    for (int k = 0; k < 6; ++k) {
        unsigned g = (unsigned)(k * 256 + t);        // 0..1535
        if (baseF4 + g < totF4) {
            unsigned r = g / 6u;                     // row within block
            unsigned c = g - r * 6u;                 // float4 column
            const float* pp = sm + r * SROW + c * 4u;
            float4 o;
            o.x = pp[0]; o.y = pp[1]; o.z = pp[2]; o.w = pp[3];
            __stcs(out4 + (baseF4 + g), o);
        }
    }
}

// ---------------------------------------------------------------------------
extern "C" void kernel_launch(void* const* d_in, const int* in_sizes, int n_in,
                              void* d_out, int out_size) {
    const float* x  = (const float*)d_in[0];
    const float* W  = (const float*)d_in[1];
    const float* P  = (const float*)d_in[2];
    const float* bv = (const float*)d_in[3];
    const float* bz = (const float*)d_in[4];
    const float* e  = (const float*)d_in[5];
    const float* ep = (const float*)d_in[6];
    const float* cx = (const float*)d_in[7];
    const float* cu = (const float*)d_in[8];
    const float* cU = (const float*)d_in[9];
    const float* v0 = (const float*)d_in[10];
    const float* X0 = (const float*)d_in[11];
    const float* U0 = (const float*)d_in[12];

    const int B  = in_sizes[0] / 8;
    const int nb = (B + RPB - 1) / RPB;

    if (nb > 0)
        cb_fused<<<nb, TPB>>>(x, (float*)d_out, B,
                              W, P, bv, bz, e, ep, cx, cu, cU, v0, X0, U0);
}

// round 7
// speedup vs baseline: 3.7477x; 3.7477x over previous
#include <cuda_runtime.h>

#define TPB  256
#define RPB  256                          // rows per block = 1 per thread
#define SROW 25                           // staging stride (odd -> conflict-free)
#define STAGE_W (RPB * SROW)              // 6400 words = 25.6KB -> 8 blocks/SM

// Coefficient tables: computed by prologue kernel into g_tab, memcpy'd into
// constant memory so the main kernel reads them over the constant/uniform
// port instead of L1TEX.
struct __align__(16) CTab {
    float4 pd[48];    // per h: pd[2h], pd[2h+1] = 8 coefs of 0.1*P[h][:]
    float4 c0[6];     // c0[h] = v0 + dt*(W@(UXr)+bv)
    float4 pz[48];    // per h: pe*sp(P[h][:])
    float4 a1[6];     // a1[h] = sp(e)*K@r + bz
    float4 zm[6];     // zm[h] = -dt*v0[h]
    float  flag;      // any(v0 != 0)
    float  pad[3];
};

__device__   CTab g_tab;
__constant__ CTab c_tab;

__device__ __forceinline__ float sp_f(float x) {      // fast softplus
    return fmaxf(x, 0.0f) + __logf(1.0f + __expf(-fabsf(x)));
}
__device__ __forceinline__ float sig_f(float x) {
    return 1.0f / (1.0f + __expf(-x));
}

// ---------------------------------------------------------------------------
// Prologue kernel: one block computes all batch-invariant values -> g_tab.
// ---------------------------------------------------------------------------
__global__ void cb_prologue(const float* __restrict__ W,  const float* __restrict__ P,
                            const float* __restrict__ bv, const float* __restrict__ bz,
                            const float* __restrict__ e,  const float* __restrict__ ep,
                            const float* __restrict__ cx, const float* __restrict__ cu,
                            const float* __restrict__ cU, const float* __restrict__ v0,
                            const float* __restrict__ X0, const float* __restrict__ U0)
{
    __shared__ float rS[24], wS[24], pkr[192], pwr[192];
    const int t = threadIdx.x;

    if (t < 24) {
        float v0v = v0[t];
        float rv  = sig_f(v0v);
        rS[t] = rv;
        float zx = 0.001f + 0.099f * sig_f(cx[t]);
        float X  = zx + (1.0f - zx) * X0[t] - U0[t] * X0[t] * rv;   // delta_t=1
        float zu   = 0.001f + 0.099f * sig_f(cu[t]);
        float Ucap = 0.9f * sig_f(cU[t]);
        float U = Ucap * zu + (1.0f - zu) * U0[t] + Ucap * (1.0f - U0[t]) * rv;
        U = fminf(fmaxf(U, Ucap), 1.0f);
        wS[t] = U * X * rv;
        ((float*)g_tab.zm)[t] = -0.1f * v0v;
    }
    if (t == 0) {
        int f = 0;
        #pragma unroll
        for (int j = 0; j < 24; ++j) f |= (v0[j] != 0.0f);
        g_tab.flag = (float)f;
    }
    __syncthreads();

    if (t < 192) {
        const int h = t >> 3;                 // 0..23
        const int i = t & 7;                  // 0..7
        float kr = 0.0f, wur = 0.0f;
        #pragma unroll
        for (int jj = 0; jj < 3; ++jj) {
            int j = i * 3 + jj;
            float Wv = W[h * 24 + j];
            kr  += sp_f(Wv) * rS[j];
            wur += Wv * wS[j];
        }
        pkr[h * 8 + i] = kr;
        pwr[h * 8 + i] = wur;
        float pe = sp_f(ep[0]);
        float Pv = P[h * 8 + i];              // P is (H, IN) row-major
        ((float*)g_tab.pd)[h * 8 + i] = 0.1f * Pv;
        ((float*)g_tab.pz)[h * 8 + i] = pe * sp_f(Pv);
    }
    __syncthreads();

    if (t < 24) {
        float kr = 0.0f, wur = 0.0f;
        #pragma unroll
        for (int k = 0; k < 8; ++k) { kr += pkr[t * 8 + k]; wur += pwr[t * 8 + k]; }
        float ke = sp_f(e[0]);
        ((float*)g_tab.a1)[t] = ke * kr + bz[t];
        ((float*)g_tab.c0)[t] = v0[t] + 0.1f * (wur + bv[t]);
    }
}

// ---------------------------------------------------------------------------
// Main kernel: 1 row/thread; coefficients from CONSTANT memory (no L1 traffic).
// ---------------------------------------------------------------------------
__global__ void __launch_bounds__(TPB, 8)
cb_main(const float* __restrict__ x, float* __restrict__ out, int B)
{
    __shared__ float sm[STAGE_W];
    const int t = threadIdx.x;
    const int row = blockIdx.x * RPB + t;       // lane <-> consecutive batch row

    float xa[8];
    #pragma unroll
    for (int i = 0; i < 8; ++i)
        xa[i] = (row < B) ? __ldcs(x + (size_t)i * (size_t)B + row) : 0.0f;

    const bool slow = (c_tab.flag != 0.0f);

    #pragma unroll
    for (int hq = 0; hq < 6; ++hq) {            // 4 h per iteration -> STS.128
        float4 v4;
        #pragma unroll
        for (int j = 0; j < 4; ++j) {
            const int h = hq * 4 + j;
            const float4 wA = c_tab.pd[2 * h];
            const float4 wB = c_tab.pd[2 * h + 1];
            float v = ((const float*)c_tab.c0)[h];
            v = fmaf(wA.x, xa[0], v);
            v = fmaf(wA.y, xa[1], v);
            v = fmaf(wA.z, xa[2], v);
            v = fmaf(wA.w, xa[3], v);
            v = fmaf(wB.x, xa[4], v);
            v = fmaf(wB.y, xa[5], v);
            v = fmaf(wB.z, xa[6], v);
            v = fmaf(wB.w, xa[7], v);

            if (slow) {
                // General case (v0 != 0): v += sig(a1 + Pz@x) * (-0.1*v0[h]).
                const float4 zA = c_tab.pz[2 * h];
                const float4 zB = c_tab.pz[2 * h + 1];
                float a = ((const float*)c_tab.a1)[h];
                a = fmaf(zA.x, xa[0], a);
                a = fmaf(zA.y, xa[1], a);
                a = fmaf(zA.z, xa[2], a);
                a = fmaf(zA.w, xa[3], a);
                a = fmaf(zB.x, xa[4], a);
                a = fmaf(zB.y, xa[5], a);
                a = fmaf(zB.z, xa[6], a);
                a = fmaf(zB.w, xa[7], a);
                v = fmaf(((const float*)c_tab.zm)[h], sig_f(a), v);
            }
            ((float*)&v4)[j] = v;
        }
        // stride-25 word rows, 16B-unaligned ok? base t*25+hq*4 is word-aligned;
        // use scalar stores when alignment can break (t odd): store as 4 floats.
        sm[t * SROW + hq * 4 + 0] = v4.x;
        sm[t * SROW + hq * 4 + 1] = v4.y;
        sm[t * SROW + hq * 4 + 2] = v4.z;
        sm[t * SROW + hq * 4 + 3] = v4.w;
    }
    __syncthreads();

    // Coalesced writeout: block owns float4 range [blockIdx*1536, +1536).
    const unsigned totF4  = (unsigned)B * 6u;
    const unsigned baseF4 = (unsigned)blockIdx.x * 1536u;
    float4* out4 = (float4*)out;
    #pragma unroll
    for (int k = 0; k < 6; ++k) {
        unsigned g = (unsigned)(k * 256 + t);        // 0..1535
        if (baseF4 + g < totF4) {
            unsigned r = g / 6u;                     // row within block
            unsigned c = g - r * 6u;                 // float4 column
            const float* pp = sm + r * SROW + c * 4u;
            float4 o;
            o.x = pp[0]; o.y = pp[1]; o.z = pp[2]; o.w = pp[3];
            __stcs(out4 + (baseF4 + g), o);
        }
    }
}

// ---------------------------------------------------------------------------
extern "C" void kernel_launch(void* const* d_in, const int* in_sizes, int n_in,
                              void* d_out, int out_size) {
    const float* x  = (const float*)d_in[0];
    const float* W  = (const float*)d_in[1];
    const float* P  = (const float*)d_in[2];
    const float* bv = (const float*)d_in[3];
    const float* bz = (const float*)d_in[4];
    const float* e  = (const float*)d_in[5];
    const float* ep = (const float*)d_in[6];
    const float* cx = (const float*)d_in[7];
    const float* cu = (const float*)d_in[8];
    const float* cU = (const float*)d_in[9];
    const float* v0 = (const float*)d_in[10];
    const float* X0 = (const float*)d_in[11];
    const float* U0 = (const float*)d_in[12];

    const int B  = in_sizes[0] / 8;
    const int nb = (B + RPB - 1) / RPB;

    cb_prologue<<<1, 256>>>(W, P, bv, bz, e, ep, cx, cu, cU, v0, X0, U0);

    // Move computed tables into constant memory (D2D async, graph-capturable).
    void* src = nullptr;
    cudaGetSymbolAddress(&src, g_tab);
    cudaMemcpyToSymbolAsync(c_tab, src, sizeof(CTab), 0,
                            cudaMemcpyDeviceToDevice, 0);

    if (nb > 0)
        cb_main<<<nb, TPB>>>(x, (float*)d_out, B);
}

// round 8
// speedup vs baseline: 5.0123x; 1.3374x over previous
#include <cuda_runtime.h>

typedef unsigned long long u64;

#define TPB  256
#define RPB  256                          // rows per block = 1 per thread
#define SROW 28                           // word stride: 16B-aligned rows, STS.128 conflict-free
#define STAGE_W (RPB * SROW)              // 7168 words = 28.7KB -> 7 blocks/SM

// Transposed coefficient tables (i-major) so one LDC.128 covers 4 h-channels.
struct __align__(16) CTabT {
    float4 pdT[48];   // pdT[i*6+q] = 0.1 * P[4q..4q+3][i]
    float4 c0[6];     // c0 quads
    float4 pzT[48];   // pe*sp(P) transposed
    float4 a1[6];
    float4 zm[6];     // -dt*v0 quads
    float  flag;
    float  pad[3];
};

__device__   CTabT g_tab;
__constant__ CTabT c_tab;

__device__ __forceinline__ float sp_f(float x) {
    return fmaxf(x, 0.0f) + __logf(1.0f + __expf(-fabsf(x)));
}
__device__ __forceinline__ float sig_f(float x) {
    return 1.0f / (1.0f + __expf(-x));
}
__device__ __forceinline__ u64 fma2(u64 a, u64 b, u64 c) {
    u64 d;
    asm("fma.rn.f32x2 %0, %1, %2, %3;" : "=l"(d) : "l"(a), "l"(b), "l"(c));
    return d;
}
__device__ __forceinline__ u64 f2u(float a, float b) {
    u64 v;
    asm("mov.b64 %0, {%1, %2};" : "=l"(v) : "f"(a), "f"(b));
    return v;
}
__device__ __forceinline__ float2 u2f(u64 v) {
    float2 r;
    asm("mov.b64 {%0, %1}, %2;" : "=f"(r.x), "=f"(r.y) : "l"(v));
    return r;
}
__device__ __forceinline__ u64 lo64(float4 v) { return f2u(v.x, v.y); }
__device__ __forceinline__ u64 hi64(float4 v) { return f2u(v.z, v.w); }

// ---------------------------------------------------------------------------
// Prologue kernel: one block computes all batch-invariant values -> g_tab.
// ---------------------------------------------------------------------------
__global__ void cb_prologue(const float* __restrict__ W,  const float* __restrict__ P,
                            const float* __restrict__ bv, const float* __restrict__ bz,
                            const float* __restrict__ e,  const float* __restrict__ ep,
                            const float* __restrict__ cx, const float* __restrict__ cu,
                            const float* __restrict__ cU, const float* __restrict__ v0,
                            const float* __restrict__ X0, const float* __restrict__ U0)
{
    __shared__ float rS[24], wS[24], pkr[192], pwr[192];
    const int t = threadIdx.x;

    if (t < 24) {
        float v0v = v0[t];
        float rv  = sig_f(v0v);
        rS[t] = rv;
        float zx = 0.001f + 0.099f * sig_f(cx[t]);
        float X  = zx + (1.0f - zx) * X0[t] - U0[t] * X0[t] * rv;   // delta_t=1
        float zu   = 0.001f + 0.099f * sig_f(cu[t]);
        float Ucap = 0.9f * sig_f(cU[t]);
        float U = Ucap * zu + (1.0f - zu) * U0[t] + Ucap * (1.0f - U0[t]) * rv;
        U = fminf(fmaxf(U, Ucap), 1.0f);
        wS[t] = U * X * rv;
        ((float*)g_tab.zm)[t] = -0.1f * v0v;
    }
    if (t == 0) {
        int f = 0;
        #pragma unroll
        for (int j = 0; j < 24; ++j) f |= (v0[j] != 0.0f);
        g_tab.flag = (float)f;
    }
    __syncthreads();

    if (t < 192) {
        const int h = t >> 3;                 // 0..23
        const int i = t & 7;                  // 0..7
        float kr = 0.0f, wur = 0.0f;
        #pragma unroll
        for (int jj = 0; jj < 3; ++jj) {
            int j = i * 3 + jj;
            float Wv = W[h * 24 + j];
            kr  += sp_f(Wv) * rS[j];
            wur += Wv * wS[j];
        }
        pkr[h * 8 + i] = kr;
        pwr[h * 8 + i] = wur;
        float pe = sp_f(ep[0]);
        float Pv = P[h * 8 + i];              // P is (H, IN) row-major
        ((float*)&g_tab.pdT[i * 6 + (h >> 2)])[h & 3] = 0.1f * Pv;
        ((float*)&g_tab.pzT[i * 6 + (h >> 2)])[h & 3] = pe * sp_f(Pv);
    }
    __syncthreads();

    if (t < 24) {
        float kr = 0.0f, wur = 0.0f;
        #pragma unroll
        for (int k = 0; k < 8; ++k) { kr += pkr[t * 8 + k]; wur += pwr[t * 8 + k]; }
        float ke = sp_f(e[0]);
        ((float*)g_tab.a1)[t] = ke * kr + bz[t];
        ((float*)g_tab.c0)[t] = v0[t] + 0.1f * (wur + bv[t]);
    }
}

// ---------------------------------------------------------------------------
// Main kernel: 1 row/thread; f32x2 packed over h-pairs; constant-port coefs;
// STS.128/LDS.128 staging at stride 28 (conflict-free, 16B aligned).
// ---------------------------------------------------------------------------
__global__ void __launch_bounds__(TPB, 7)
cb_main(const float* __restrict__ x, float* __restrict__ out, int B)
{
    __shared__ float sm[STAGE_W];
    const int t = threadIdx.x;
    const int row = blockIdx.x * RPB + t;       // lane <-> consecutive batch row

    // x packed (x, x) once: both f32x2 lanes are h-channels of the same row.
    u64 xp[8];
    #pragma unroll
    for (int i = 0; i < 8; ++i) {
        float v = (row < B) ? __ldcs(x + (size_t)i * (size_t)B + row) : 0.0f;
        xp[i] = f2u(v, v);
    }

    const bool slow = (c_tab.flag != 0.0f);

    #pragma unroll
    for (int q = 0; q < 6; ++q) {               // quad of h: 4q .. 4q+3
        const float4 c0q = c_tab.c0[q];
        u64 a01 = lo64(c0q);
        u64 a23 = hi64(c0q);
        #pragma unroll
        for (int i = 0; i < 8; ++i) {
            const float4 p = c_tab.pdT[i * 6 + q];
            a01 = fma2(lo64(p), xp[i], a01);
            a23 = fma2(hi64(p), xp[i], a23);
        }

        if (slow) {
            // General case (v0 != 0): v += sig(a1 + Pz@x) * (-0.1*v0[h]). Exact.
            const float4 a1q = c_tab.a1[q];
            u64 z01 = lo64(a1q);
            u64 z23 = hi64(a1q);
            #pragma unroll
            for (int i = 0; i < 8; ++i) {
                const float4 p = c_tab.pzT[i * 6 + q];
                z01 = fma2(lo64(p), xp[i], z01);
                z23 = fma2(hi64(p), xp[i], z23);
            }
            const float4 zmq = c_tab.zm[q];
            float2 v01 = u2f(a01), v23 = u2f(a23);
            float2 s01 = u2f(z01), s23 = u2f(z23);
            v01.x = fmaf(zmq.x, sig_f(s01.x), v01.x);
            v01.y = fmaf(zmq.y, sig_f(s01.y), v01.y);
            v23.x = fmaf(zmq.z, sig_f(s23.x), v23.x);
            v23.y = fmaf(zmq.w, sig_f(s23.y), v23.y);
            a01 = f2u(v01.x, v01.y);
            a23 = f2u(v23.x, v23.y);
        }

        // STS.128: (28t + 4q)*4B is 16B-aligned; stride-28 phases conflict-free.
        ulonglong2 st; st.x = a01; st.y = a23;
        *reinterpret_cast<ulonglong2*>(&sm[t * SROW + 4 * q]) = st;
    }
    __syncthreads();

    // Coalesced writeout: block owns float4 range [blockIdx*1536, +1536).
    const unsigned totF4  = (unsigned)B * 6u;
    const unsigned baseF4 = (unsigned)blockIdx.x * 1536u;
    float4* out4 = (float4*)out;
    #pragma unroll
    for (int k = 0; k < 6; ++k) {
        unsigned g = (unsigned)(k * 256 + t);        // 0..1535
        if (baseF4 + g < totF4) {
            unsigned r = g / 6u;                     // row within block
            unsigned c = g - r * 6u;                 // float4 column
            float4 o = *reinterpret_cast<const float4*>(&sm[r * SROW + 4u * c]);
            __stcs(out4 + (baseF4 + g), o);
        }
    }
}

// ---------------------------------------------------------------------------
extern "C" void kernel_launch(void* const* d_in, const int* in_sizes, int n_in,
                              void* d_out, int out_size) {
    const float* x  = (const float*)d_in[0];
    const float* W  = (const float*)d_in[1];
    const float* P  = (const float*)d_in[2];
    const float* bv = (const float*)d_in[3];
    const float* bz = (const float*)d_in[4];
    const float* e  = (const float*)d_in[5];
    const float* ep = (const float*)d_in[6];
    const float* cx = (const float*)d_in[7];
    const float* cu = (const float*)d_in[8];
    const float* cU = (const float*)d_in[9];
    const float* v0 = (const float*)d_in[10];
    const float* X0 = (const float*)d_in[11];
    const float* U0 = (const float*)d_in[12];

    const int B  = in_sizes[0] / 8;
    const int nb = (B + RPB - 1) / RPB;

    cb_prologue<<<1, 256>>>(W, P, bv, bz, e, ep, cx, cu, cU, v0, X0, U0);

    void* src = nullptr;
    cudaGetSymbolAddress(&src, g_tab);
    cudaMemcpyToSymbolAsync(c_tab, src, sizeof(CTabT), 0,
                            cudaMemcpyDeviceToDevice, 0);

    if (nb > 0)
        cb_main<<<nb, TPB>>>(x, (float*)d_out, B);
}